// round 1
// baseline (speedup 1.0000x reference)
#include <cuda_runtime.h>
#include <math.h>

#define NQ 2048
#define NC 4096
#define DIM 512
#define NH 8
#define HD 64
#define LN_EPS 1e-5f

// -------- scratch (no allocation allowed) --------
__device__ float g_Qp[NQ * DIM];
__device__ float g_Kp[NC * DIM];
__device__ float g_Vp[NC * DIM];
__device__ float g_ctx[NQ * DIM];
__device__ float g_x[NQ * DIM];

// ============================================================
// GEMM: C[M,N] = A[M,K] @ B[N,K]^T + bias[N]  (+ optional residual R[M,N])
// BM=BN=64, BK=16, 256 threads, 4x4 per thread
// ============================================================
template <bool RESID>
__global__ void gemm_bias_kernel(const float* __restrict__ A,
                                 const float* __restrict__ B,
                                 const float* __restrict__ bias,
                                 const float* __restrict__ R,
                                 float* __restrict__ C,
                                 int M, int N, int K)
{
    __shared__ float As[16][64];  // [k][m]
    __shared__ float Bs[16][64];  // [k][n]

    const int tid = threadIdx.x;
    const int tx = tid & 15;       // 0..15 -> n
    const int ty = tid >> 4;       // 0..15 -> m
    const int m0 = blockIdx.y * 64;
    const int n0 = blockIdx.x * 64;

    // load mapping: row = tid>>2 (0..63), col4 = (tid&3)*4 (0..12)
    const int lr = tid >> 2;
    const int lc = (tid & 3) * 4;

    float acc[4][4] = {};

    for (int k0 = 0; k0 < K; k0 += 16) {
        float4 av = *(const float4*)&A[(size_t)(m0 + lr) * K + k0 + lc];
        float4 bv = *(const float4*)&B[(size_t)(n0 + lr) * K + k0 + lc];
        As[lc + 0][lr] = av.x; As[lc + 1][lr] = av.y;
        As[lc + 2][lr] = av.z; As[lc + 3][lr] = av.w;
        Bs[lc + 0][lr] = bv.x; Bs[lc + 1][lr] = bv.y;
        Bs[lc + 2][lr] = bv.z; Bs[lc + 3][lr] = bv.w;
        __syncthreads();

#pragma unroll
        for (int kk = 0; kk < 16; kk++) {
            float4 a4 = *(const float4*)&As[kk][ty * 4];
            float4 b4 = *(const float4*)&Bs[kk][tx * 4];
            float a[4] = {a4.x, a4.y, a4.z, a4.w};
            float b[4] = {b4.x, b4.y, b4.z, b4.w};
#pragma unroll
            for (int i = 0; i < 4; i++)
#pragma unroll
                for (int j = 0; j < 4; j++)
                    acc[i][j] = fmaf(a[i], b[j], acc[i][j]);
        }
        __syncthreads();
    }

#pragma unroll
    for (int i = 0; i < 4; i++) {
        int m = m0 + ty * 4 + i;
#pragma unroll
        for (int j = 0; j < 4; j++) {
            int n = n0 + tx * 4 + j;
            float v = acc[i][j] + bias[n];
            if (RESID) v += R[(size_t)m * N + n];
            C[(size_t)m * N + n] = v;
        }
    }
}

// ============================================================
// Fused flash attention with distance bias.
// grid: (NQ/64, NH), 256 threads.
// Per block: 64 queries of one head; stream context in tiles of 128.
// ============================================================
#define TC 128
#define S_STRIDE 132   // padded to kill bank conflicts on row-major P reads

// dynamic smem layout (floats):
//   sQ   [64*64]       Q tile, [r][k]
//   sKT  [64*128]      K tile transposed, [k][c]
//   sV   [128*64]      V tile, [c][d]
//   sS   [64*132]      scores / probs (padded stride)
//   sQC  [64*2]        query coords
//   sCC  [128*2]       context coords
//   sM,sL,sAlpha [64]  online-softmax state
#define ATTN_SMEM_FLOATS (64*64 + 64*128 + 128*64 + 64*S_STRIDE + 128 + 256 + 192)
#define ATTN_SMEM_BYTES (ATTN_SMEM_FLOATS * 4)

__global__ void attn_kernel(const float* __restrict__ Qp,
                            const float* __restrict__ Kp,
                            const float* __restrict__ Vp,
                            const float* __restrict__ qcoord,
                            const float* __restrict__ ccoord,
                            const float* __restrict__ log_scale,
                            const float* __restrict__ bias_ph,
                            float* __restrict__ ctx)
{
    extern __shared__ float sm[];
    float* sQ     = sm;
    float* sKT    = sQ  + 64 * 64;
    float* sV     = sKT + 64 * 128;
    float* sS     = sV  + 128 * 64;
    float* sQC    = sS  + 64 * S_STRIDE;
    float* sCC    = sQC + 128;
    float* sM     = sCC + 256;
    float* sL     = sM + 64;
    float* sAlpha = sL + 64;

    const int h  = blockIdx.y;
    const int q0 = blockIdx.x * 64;
    const int tid = threadIdx.x;
    const int lane = tid & 31;
    const int wid  = tid >> 5;

    const float coef = -__expf(log_scale[0]) * bias_ph[h];
    const float scale = 0.125f;  // 1/sqrt(64)

    // ---- load Q tile ----
    {
        int r = tid >> 2, k0 = (tid & 3) * 16;
        const float* src = &Qp[(size_t)(q0 + r) * DIM + h * HD + k0];
        float* dst = &sQ[r * 64 + k0];
#pragma unroll
        for (int i = 0; i < 16; i += 4)
            *(float4*)&dst[i] = *(const float4*)&src[i];
    }
    if (tid < 64) {
        sQC[tid * 2 + 0] = qcoord[(q0 + tid) * 2 + 0];
        sQC[tid * 2 + 1] = qcoord[(q0 + tid) * 2 + 1];
        sM[tid] = -INFINITY;
        sL[tid] = 0.0f;
        sAlpha[tid] = 1.0f;
    }
    __syncthreads();

    // per-thread output accumulator: row = tid>>2, dims od0..od0+15
    const int orow = tid >> 2;
    const int od0  = (tid & 3) * 16;
    float o[16] = {};

    for (int c0 = 0; c0 < NC; c0 += TC) {
        // ---- load K (transposed) and V tiles, context coords ----
        {
            int c = tid >> 1, kb = (tid & 1) * 32;
            const float* src = &Kp[(size_t)(c0 + c) * DIM + h * HD + kb];
#pragma unroll
            for (int k = 0; k < 32; k++)
                sKT[(kb + k) * TC + c] = src[k];
        }
        {
            int c = tid >> 1, db = (tid & 1) * 32;
            const float4* src = (const float4*)&Vp[(size_t)(c0 + c) * DIM + h * HD + db];
            float4* dst = (float4*)&sV[c * 64 + db];
#pragma unroll
            for (int i = 0; i < 8; i++) dst[i] = src[i];
        }
        if (tid < 128) {
            sCC[tid * 2 + 0] = ccoord[(c0 + tid) * 2 + 0];
            sCC[tid * 2 + 1] = ccoord[(c0 + tid) * 2 + 1];
        }
        __syncthreads();

        // ---- compute scores S = Q K^T * scale + distance bias ----
        {
            const int ty = tid >> 4, tx = tid & 15;
            float accS[4][8] = {};
#pragma unroll 4
            for (int k = 0; k < 64; k++) {
                float a[4], b[8];
#pragma unroll
                for (int i = 0; i < 4; i++) a[i] = sQ[(ty * 4 + i) * 64 + k];
#pragma unroll
                for (int j = 0; j < 8; j++) b[j] = sKT[k * TC + tx + 16 * j];
#pragma unroll
                for (int i = 0; i < 4; i++)
#pragma unroll
                    for (int j = 0; j < 8; j++)
                        accS[i][j] = fmaf(a[i], b[j], accS[i][j]);
            }
#pragma unroll
            for (int i = 0; i < 4; i++) {
                int r = ty * 4 + i;
                float qx = sQC[r * 2], qy = sQC[r * 2 + 1];
#pragma unroll
                for (int j = 0; j < 8; j++) {
                    int c = tx + 16 * j;
                    float dx = qx - sCC[c * 2];
                    float dy = qy - sCC[c * 2 + 1];
                    float dist = sqrtf(dx * dx + dy * dy);
                    sS[r * S_STRIDE + c] = accS[i][j] * scale + coef * dist;
                }
            }
        }
        __syncthreads();

        // ---- online softmax (warp wid owns rows 8*wid .. 8*wid+7) ----
        {
#pragma unroll
            for (int rr = 0; rr < 8; rr++) {
                int r = wid * 8 + rr;
                float s0 = sS[r * S_STRIDE + lane +  0];
                float s1 = sS[r * S_STRIDE + lane + 32];
                float s2 = sS[r * S_STRIDE + lane + 64];
                float s3 = sS[r * S_STRIDE + lane + 96];
                float mx = fmaxf(fmaxf(s0, s1), fmaxf(s2, s3));
#pragma unroll
                for (int off = 16; off > 0; off >>= 1)
                    mx = fmaxf(mx, __shfl_xor_sync(0xffffffffu, mx, off));
                float m_old = sM[r];
                float m_new = fmaxf(m_old, mx);
                float p0 = __expf(s0 - m_new);
                float p1 = __expf(s1 - m_new);
                float p2 = __expf(s2 - m_new);
                float p3 = __expf(s3 - m_new);
                float ps = p0 + p1 + p2 + p3;
#pragma unroll
                for (int off = 16; off > 0; off >>= 1)
                    ps += __shfl_xor_sync(0xffffffffu, ps, off);
                sS[r * S_STRIDE + lane +  0] = p0;
                sS[r * S_STRIDE + lane + 32] = p1;
                sS[r * S_STRIDE + lane + 64] = p2;
                sS[r * S_STRIDE + lane + 96] = p3;
                if (lane == 0) {
                    float alpha = __expf(m_old - m_new);
                    sAlpha[r] = alpha;
                    sL[r] = sL[r] * alpha + ps;
                    sM[r] = m_new;
                }
            }
        }
        __syncthreads();

        // ---- accumulate O = O*alpha + P @ V ----
        {
            float alpha = sAlpha[orow];
#pragma unroll
            for (int i = 0; i < 16; i++) o[i] *= alpha;
#pragma unroll 4
            for (int c = 0; c < TC; c++) {
                float p = sS[orow * S_STRIDE + c];
                const float* vr = &sV[c * 64 + od0];
#pragma unroll
                for (int i = 0; i < 16; i++)
                    o[i] = fmaf(p, vr[i], o[i]);
            }
        }
        __syncthreads();
    }

    // ---- normalize and write ----
    float rl = 1.0f / sL[orow];
    float* dst = &ctx[(size_t)(q0 + orow) * DIM + h * HD + od0];
#pragma unroll
    for (int i = 0; i < 16; i++) dst[i] = o[i] * rl;
}

// ============================================================
// LayerNorm: one block per row (512 dims), 128 threads x 4 elems
// ============================================================
__global__ void ln_kernel(const float* __restrict__ X,
                          const float* __restrict__ gam,
                          const float* __restrict__ bet,
                          float* __restrict__ out)
{
    __shared__ float red[32];
    const int row = blockIdx.x;
    const int tid = threadIdx.x;
    const float* x = &X[(size_t)row * DIM];

    float v[4];
    float s = 0.0f;
#pragma unroll
    for (int i = 0; i < 4; i++) {
        v[i] = x[tid + i * 128];
        s += v[i];
    }
    // block reduce sum
#pragma unroll
    for (int off = 16; off > 0; off >>= 1)
        s += __shfl_xor_sync(0xffffffffu, s, off);
    if ((tid & 31) == 0) red[tid >> 5] = s;
    __syncthreads();
    if (tid < 32) {
        float t = (tid < 4) ? red[tid] : 0.0f;
#pragma unroll
        for (int off = 2; off > 0; off >>= 1)
            t += __shfl_xor_sync(0xffffffffu, t, off);
        if (tid == 0) red[0] = t;
    }
    __syncthreads();
    float mu = red[0] * (1.0f / DIM);

    float s2 = 0.0f;
#pragma unroll
    for (int i = 0; i < 4; i++) {
        float d = v[i] - mu;
        s2 += d * d;
    }
#pragma unroll
    for (int off = 16; off > 0; off >>= 1)
        s2 += __shfl_xor_sync(0xffffffffu, s2, off);
    __syncthreads();
    if ((tid & 31) == 0) red[tid >> 5] = s2;
    __syncthreads();
    if (tid < 32) {
        float t = (tid < 4) ? red[tid] : 0.0f;
#pragma unroll
        for (int off = 2; off > 0; off >>= 1)
            t += __shfl_xor_sync(0xffffffffu, t, off);
        if (tid == 0) red[0] = t;
    }
    __syncthreads();
    float rstd = rsqrtf(red[0] * (1.0f / DIM) + LN_EPS);

#pragma unroll
    for (int i = 0; i < 4; i++) {
        int c = tid + i * 128;
        out[(size_t)row * DIM + c] = (v[i] - mu) * rstd * gam[c] + bet[c];
    }
}

// ============================================================
extern "C" void kernel_launch(void* const* d_in, const int* in_sizes, int n_in,
                              void* d_out, int out_size)
{
    const float* query   = (const float*)d_in[0];   // (NQ, D)
    const float* context = (const float*)d_in[1];   // (NC, D)
    const float* qcoord  = (const float*)d_in[2];   // (NQ, 2)
    const float* ccoord  = (const float*)d_in[3];   // (NC, 2)
    const float* Wq = (const float*)d_in[4];
    const float* bq = (const float*)d_in[5];
    const float* Wk = (const float*)d_in[6];
    const float* bk = (const float*)d_in[7];
    const float* Wv = (const float*)d_in[8];
    const float* bv = (const float*)d_in[9];
    const float* Wo = (const float*)d_in[10];
    const float* bo = (const float*)d_in[11];
    const float* ln_g = (const float*)d_in[12];
    const float* ln_b = (const float*)d_in[13];
    const float* log_scale = (const float*)d_in[14];
    const float* bias_ph   = (const float*)d_in[15];
    float* out = (float*)d_out;

    float *Qp, *Kp, *Vp, *ctx, *x;
    cudaGetSymbolAddress((void**)&Qp,  g_Qp);
    cudaGetSymbolAddress((void**)&Kp,  g_Kp);
    cudaGetSymbolAddress((void**)&Vp,  g_Vp);
    cudaGetSymbolAddress((void**)&ctx, g_ctx);
    cudaGetSymbolAddress((void**)&x,   g_x);

    // projections
    gemm_bias_kernel<false><<<dim3(DIM / 64, NQ / 64), 256>>>(
        query, Wq, bq, nullptr, Qp, NQ, DIM, DIM);
    gemm_bias_kernel<false><<<dim3(DIM / 64, NC / 64), 256>>>(
        context, Wk, bk, nullptr, Kp, NC, DIM, DIM);
    gemm_bias_kernel<false><<<dim3(DIM / 64, NC / 64), 256>>>(
        context, Wv, bv, nullptr, Vp, NC, DIM, DIM);

    // fused attention (needs >48KB dynamic smem)
    cudaFuncSetAttribute(attn_kernel,
                         cudaFuncAttributeMaxDynamicSharedMemorySize,
                         ATTN_SMEM_BYTES);
    attn_kernel<<<dim3(NQ / 64, NH), 256, ATTN_SMEM_BYTES>>>(
        Qp, Kp, Vp, qcoord, ccoord, log_scale, bias_ph, ctx);

    // output projection + residual
    gemm_bias_kernel<true><<<dim3(DIM / 64, NQ / 64), 256>>>(
        ctx, Wo, bo, query, x, NQ, DIM, DIM);

    // LayerNorm
    ln_kernel<<<NQ, 128>>>(x, ln_g, ln_b, out);
}

// round 2
// speedup vs baseline: 1.2387x; 1.2387x over previous
#include <cuda_runtime.h>
#include <math.h>

#define NQ 2048
#define NC 4096
#define DIM 512
#define NH 8
#define HD 64
#define LN_EPS 1e-5f

// -------- scratch (no allocation allowed) --------
__device__ float g_QpT[DIM * NQ];   // [h*64+k][q]  (transposed)
__device__ float g_KpT[DIM * NC];   // [h*64+k][c]  (transposed)
__device__ float g_Vp[NC * DIM];    // [c][d]       (natural)
__device__ float g_ctx[NQ * DIM];
__device__ float g_x[NQ * DIM];

// ============================================================
// GEMM: C = A[M,K] @ B[N,K]^T + bias[N] (+residual)
// TRANSOUT: write C^T (C[n*M+m]) instead of C[m*N+n]
// ============================================================
template <bool RESID, bool TRANSOUT>
__global__ void gemm_bias_kernel(const float* __restrict__ A,
                                 const float* __restrict__ B,
                                 const float* __restrict__ bias,
                                 const float* __restrict__ R,
                                 float* __restrict__ C,
                                 int M, int N, int K)
{
    __shared__ float As[16][64];  // [k][m]
    __shared__ float Bs[16][64];  // [k][n]

    const int tid = threadIdx.x;
    const int tx = tid & 15;
    const int ty = tid >> 4;
    const int m0 = blockIdx.y * 64;
    const int n0 = blockIdx.x * 64;

    const int lr = tid >> 2;
    const int lc = (tid & 3) * 4;

    float acc[4][4] = {};

    for (int k0 = 0; k0 < K; k0 += 16) {
        float4 av = *(const float4*)&A[(size_t)(m0 + lr) * K + k0 + lc];
        float4 bv = *(const float4*)&B[(size_t)(n0 + lr) * K + k0 + lc];
        As[lc + 0][lr] = av.x; As[lc + 1][lr] = av.y;
        As[lc + 2][lr] = av.z; As[lc + 3][lr] = av.w;
        Bs[lc + 0][lr] = bv.x; Bs[lc + 1][lr] = bv.y;
        Bs[lc + 2][lr] = bv.z; Bs[lc + 3][lr] = bv.w;
        __syncthreads();

#pragma unroll
        for (int kk = 0; kk < 16; kk++) {
            float4 a4 = *(const float4*)&As[kk][ty * 4];
            float4 b4 = *(const float4*)&Bs[kk][tx * 4];
            float a[4] = {a4.x, a4.y, a4.z, a4.w};
            float b[4] = {b4.x, b4.y, b4.z, b4.w};
#pragma unroll
            for (int i = 0; i < 4; i++)
#pragma unroll
                for (int j = 0; j < 4; j++)
                    acc[i][j] = fmaf(a[i], b[j], acc[i][j]);
        }
        __syncthreads();
    }

#pragma unroll
    for (int i = 0; i < 4; i++) {
        int m = m0 + ty * 4 + i;
#pragma unroll
        for (int j = 0; j < 4; j++) {
            int n = n0 + tx * 4 + j;
            float v = acc[i][j] + bias[n];
            if (RESID) v += R[(size_t)m * N + n];
            if (TRANSOUT) C[(size_t)n * M + m] = v;
            else          C[(size_t)m * N + n] = v;
        }
    }
}

// ============================================================
// Fused flash attention with distance bias (fp32, vectorized LDS).
// grid: (NQ/64, NH), 256 threads, 3 CTAs/SM.
// Q, K come in pre-transposed [h*64+k][seq] layout.
// ============================================================
#define TC 64
#define STRD 68  // padded stride (floats), keeps 16B alignment

// dynamic smem: sQT[64][68] sKT[64][68] sV[64][68] sS[64][68] + coords/state
#define ATTN_SMEM_FLOATS (4 * 64 * STRD + 128 + 128 + 192)
#define ATTN_SMEM_BYTES (ATTN_SMEM_FLOATS * 4)

__global__ void __launch_bounds__(256, 3)
attn_kernel(const float* __restrict__ QpT,
            const float* __restrict__ KpT,
            const float* __restrict__ Vp,
            const float* __restrict__ qcoord,
            const float* __restrict__ ccoord,
            const float* __restrict__ log_scale,
            const float* __restrict__ bias_ph,
            float* __restrict__ ctx)
{
    extern __shared__ float sm[];
    float* sQT    = sm;                    // [k][r]
    float* sKT    = sQT + 64 * STRD;       // [k][c]
    float* sV     = sKT + 64 * STRD;       // [c][d]
    float* sS     = sV  + 64 * STRD;       // [r][c]
    float* sQC    = sS  + 64 * STRD;       // 128
    float* sCC    = sQC + 128;             // 128
    float* sM     = sCC + 128;
    float* sL     = sM + 64;
    float* sAlpha = sL + 64;

    const int h   = blockIdx.y;
    const int q0  = blockIdx.x * 64;
    const int tid = threadIdx.x;
    const int lane = tid & 31;
    const int wid  = tid >> 5;

    const float coef  = -__expf(log_scale[0]) * bias_ph[h];
    const float scale = 0.125f;  // 1/sqrt(64)

    // ---- load Q tile (transposed layout, coalesced) ----
    {
        int k  = tid >> 2;
        int r0 = (tid & 3) * 16;
        const float* src = &QpT[(size_t)(h * HD + k) * NQ + q0 + r0];
        float* dst = &sQT[k * STRD + r0];
#pragma unroll
        for (int i = 0; i < 16; i += 4)
            *(float4*)&dst[i] = *(const float4*)&src[i];
    }
    if (tid < 64) {
        sQC[tid * 2 + 0] = qcoord[(q0 + tid) * 2 + 0];
        sQC[tid * 2 + 1] = qcoord[(q0 + tid) * 2 + 1];
        sM[tid] = -INFINITY;
        sL[tid] = 0.0f;
        sAlpha[tid] = 1.0f;
    }
    __syncthreads();

    const int ty = tid >> 4;       // 0..15 (row group)
    const int tx = tid & 15;       // 0..15 (col group)
    const int orow = tid >> 2;     // 0..63
    const int od0  = (tid & 3) * 16;
    float o[16] = {};

    for (int c0 = 0; c0 < NC; c0 += TC) {
        // ---- load K tile (transposed layout, coalesced) + V tile ----
        {
            int k  = tid >> 2;
            int cl = (tid & 3) * 16;
            const float* src = &KpT[(size_t)(h * HD + k) * NC + c0 + cl];
            float* dst = &sKT[k * STRD + cl];
#pragma unroll
            for (int i = 0; i < 16; i += 4)
                *(float4*)&dst[i] = *(const float4*)&src[i];
        }
        {
            int c  = tid >> 2;
            int d0 = (tid & 3) * 16;
            const float* src = &Vp[(size_t)(c0 + c) * DIM + h * HD + d0];
            float* dst = &sV[c * STRD + d0];
#pragma unroll
            for (int i = 0; i < 16; i += 4)
                *(float4*)&dst[i] = *(const float4*)&src[i];
        }
        if (tid < 64) {
            sCC[tid * 2 + 0] = ccoord[(c0 + tid) * 2 + 0];
            sCC[tid * 2 + 1] = ccoord[(c0 + tid) * 2 + 1];
        }
        __syncthreads();

        // ---- scores: acc[i][j] = sum_k Q[r][k] K[c][k], vectorized LDS ----
        {
            float acc[4][4] = {};
#pragma unroll 16
            for (int k = 0; k < 64; k++) {
                float4 a4 = *(const float4*)&sQT[k * STRD + ty * 4];
                float4 b4 = *(const float4*)&sKT[k * STRD + tx * 4];
                float a[4] = {a4.x, a4.y, a4.z, a4.w};
                float b[4] = {b4.x, b4.y, b4.z, b4.w};
#pragma unroll
                for (int i = 0; i < 4; i++)
#pragma unroll
                    for (int j = 0; j < 4; j++)
                        acc[i][j] = fmaf(a[i], b[j], acc[i][j]);
            }
#pragma unroll
            for (int i = 0; i < 4; i++) {
                int r = ty * 4 + i;
                float qx = sQC[r * 2], qy = sQC[r * 2 + 1];
                float4 sv;
                float tmp[4];
#pragma unroll
                for (int j = 0; j < 4; j++) {
                    int c = tx * 4 + j;
                    float dx = qx - sCC[c * 2];
                    float dy = qy - sCC[c * 2 + 1];
                    float dist = sqrtf(dx * dx + dy * dy);
                    tmp[j] = fmaf(acc[i][j], scale, coef * dist);
                }
                sv.x = tmp[0]; sv.y = tmp[1]; sv.z = tmp[2]; sv.w = tmp[3];
                *(float4*)&sS[r * STRD + tx * 4] = sv;
            }
        }
        __syncthreads();

        // ---- online softmax: warp wid owns rows wid*8 .. wid*8+7 ----
        {
#pragma unroll
            for (int rr = 0; rr < 8; rr++) {
                int r = wid * 8 + rr;
                float s0 = sS[r * STRD + lane];
                float s1 = sS[r * STRD + lane + 32];
                float mx = fmaxf(s0, s1);
#pragma unroll
                for (int off = 16; off > 0; off >>= 1)
                    mx = fmaxf(mx, __shfl_xor_sync(0xffffffffu, mx, off));
                float m_old = sM[r];
                float m_new = fmaxf(m_old, mx);
                float p0 = __expf(s0 - m_new);
                float p1 = __expf(s1 - m_new);
                float ps = p0 + p1;
#pragma unroll
                for (int off = 16; off > 0; off >>= 1)
                    ps += __shfl_xor_sync(0xffffffffu, ps, off);
                sS[r * STRD + lane]      = p0;
                sS[r * STRD + lane + 32] = p1;
                if (lane == 0) {
                    float alpha = __expf(m_old - m_new);
                    sAlpha[r] = alpha;
                    sL[r] = sL[r] * alpha + ps;
                    sM[r] = m_new;
                }
            }
        }
        __syncthreads();

        // ---- O = O*alpha + P @ V, vectorized sV reads ----
        {
            float alpha = sAlpha[orow];
#pragma unroll
            for (int i = 0; i < 16; i++) o[i] *= alpha;
#pragma unroll 8
            for (int c = 0; c < TC; c++) {
                float p = sS[orow * STRD + c];
                const float* vr = &sV[c * STRD + od0];
                float4 v0 = *(const float4*)&vr[0];
                float4 v1 = *(const float4*)&vr[4];
                float4 v2 = *(const float4*)&vr[8];
                float4 v3 = *(const float4*)&vr[12];
                o[0]  = fmaf(p, v0.x, o[0]);  o[1]  = fmaf(p, v0.y, o[1]);
                o[2]  = fmaf(p, v0.z, o[2]);  o[3]  = fmaf(p, v0.w, o[3]);
                o[4]  = fmaf(p, v1.x, o[4]);  o[5]  = fmaf(p, v1.y, o[5]);
                o[6]  = fmaf(p, v1.z, o[6]);  o[7]  = fmaf(p, v1.w, o[7]);
                o[8]  = fmaf(p, v2.x, o[8]);  o[9]  = fmaf(p, v2.y, o[9]);
                o[10] = fmaf(p, v2.z, o[10]); o[11] = fmaf(p, v2.w, o[11]);
                o[12] = fmaf(p, v3.x, o[12]); o[13] = fmaf(p, v3.y, o[13]);
                o[14] = fmaf(p, v3.z, o[14]); o[15] = fmaf(p, v3.w, o[15]);
            }
        }
        __syncthreads();
    }

    // ---- normalize and write ----
    float rl = 1.0f / sL[orow];
    float* dst = &ctx[(size_t)(q0 + orow) * DIM + h * HD + od0];
#pragma unroll
    for (int i = 0; i < 16; i++) dst[i] = o[i] * rl;
}

// ============================================================
// LayerNorm: one block per row (512 dims), 128 threads x 4 elems
// ============================================================
__global__ void ln_kernel(const float* __restrict__ X,
                          const float* __restrict__ gam,
                          const float* __restrict__ bet,
                          float* __restrict__ out)
{
    __shared__ float red[32];
    const int row = blockIdx.x;
    const int tid = threadIdx.x;
    const float* x = &X[(size_t)row * DIM];

    float v[4];
    float s = 0.0f;
#pragma unroll
    for (int i = 0; i < 4; i++) {
        v[i] = x[tid + i * 128];
        s += v[i];
    }
#pragma unroll
    for (int off = 16; off > 0; off >>= 1)
        s += __shfl_xor_sync(0xffffffffu, s, off);
    if ((tid & 31) == 0) red[tid >> 5] = s;
    __syncthreads();
    if (tid < 32) {
        float t = (tid < 4) ? red[tid] : 0.0f;
#pragma unroll
        for (int off = 2; off > 0; off >>= 1)
            t += __shfl_xor_sync(0xffffffffu, t, off);
        if (tid == 0) red[0] = t;
    }
    __syncthreads();
    float mu = red[0] * (1.0f / DIM);

    float s2 = 0.0f;
#pragma unroll
    for (int i = 0; i < 4; i++) {
        float d = v[i] - mu;
        s2 += d * d;
    }
#pragma unroll
    for (int off = 16; off > 0; off >>= 1)
        s2 += __shfl_xor_sync(0xffffffffu, s2, off);
    __syncthreads();
    if ((tid & 31) == 0) red[tid >> 5] = s2;
    __syncthreads();
    if (tid < 32) {
        float t = (tid < 4) ? red[tid] : 0.0f;
#pragma unroll
        for (int off = 2; off > 0; off >>= 1)
            t += __shfl_xor_sync(0xffffffffu, t, off);
        if (tid == 0) red[0] = t;
    }
    __syncthreads();
    float rstd = rsqrtf(red[0] * (1.0f / DIM) + LN_EPS);

#pragma unroll
    for (int i = 0; i < 4; i++) {
        int c = tid + i * 128;
        out[(size_t)row * DIM + c] = (v[i] - mu) * rstd * gam[c] + bet[c];
    }
}

// ============================================================
extern "C" void kernel_launch(void* const* d_in, const int* in_sizes, int n_in,
                              void* d_out, int out_size)
{
    const float* query   = (const float*)d_in[0];
    const float* context = (const float*)d_in[1];
    const float* qcoord  = (const float*)d_in[2];
    const float* ccoord  = (const float*)d_in[3];
    const float* Wq = (const float*)d_in[4];
    const float* bq = (const float*)d_in[5];
    const float* Wk = (const float*)d_in[6];
    const float* bk = (const float*)d_in[7];
    const float* Wv = (const float*)d_in[8];
    const float* bv = (const float*)d_in[9];
    const float* Wo = (const float*)d_in[10];
    const float* bo = (const float*)d_in[11];
    const float* ln_g = (const float*)d_in[12];
    const float* ln_b = (const float*)d_in[13];
    const float* log_scale = (const float*)d_in[14];
    const float* bias_ph   = (const float*)d_in[15];
    float* out = (float*)d_out;

    float *QpT, *KpT, *Vp, *ctx, *x;
    cudaGetSymbolAddress((void**)&QpT, g_QpT);
    cudaGetSymbolAddress((void**)&KpT, g_KpT);
    cudaGetSymbolAddress((void**)&Vp,  g_Vp);
    cudaGetSymbolAddress((void**)&ctx, g_ctx);
    cudaGetSymbolAddress((void**)&x,   g_x);

    // projections (Q, K written transposed for the attention kernel)
    gemm_bias_kernel<false, true><<<dim3(DIM / 64, NQ / 64), 256>>>(
        query, Wq, bq, nullptr, QpT, NQ, DIM, DIM);
    gemm_bias_kernel<false, true><<<dim3(DIM / 64, NC / 64), 256>>>(
        context, Wk, bk, nullptr, KpT, NC, DIM, DIM);
    gemm_bias_kernel<false, false><<<dim3(DIM / 64, NC / 64), 256>>>(
        context, Wv, bv, nullptr, Vp, NC, DIM, DIM);

    // fused attention
    cudaFuncSetAttribute(attn_kernel,
                         cudaFuncAttributeMaxDynamicSharedMemorySize,
                         ATTN_SMEM_BYTES);
    attn_kernel<<<dim3(NQ / 64, NH), 256, ATTN_SMEM_BYTES>>>(
        QpT, KpT, Vp, qcoord, ccoord, log_scale, bias_ph, ctx);

    // output projection + residual
    gemm_bias_kernel<true, false><<<dim3(DIM / 64, NQ / 64), 256>>>(
        ctx, Wo, bo, query, x, NQ, DIM, DIM);

    // LayerNorm
    ln_kernel<<<NQ, 128>>>(x, ln_g, ln_b, out);
}

// round 3
// speedup vs baseline: 1.2409x; 1.0017x over previous
#include <cuda_runtime.h>
#include <math.h>

#define NQ 2048
#define NC 4096
#define DIM 512
#define NH 8
#define HD 64
#define LN_EPS 1e-5f

// -------- scratch (no allocation allowed) --------
__device__ float g_QpT[DIM * NQ];   // [h*64+k][q]  (transposed)
__device__ float g_KpT[DIM * NC];   // [h*64+k][c]  (transposed)
__device__ float g_Vp[NC * DIM];    // [c][d]       (natural)
__device__ float g_ctx[NQ * DIM];
__device__ float g_x[NQ * DIM];

// ============================================================
// GEMM: C = A[M,K] @ B[N,K]^T + bias[N] (+residual)
// TRANSOUT: write C^T (C[n*M+m]) instead of C[m*N+n]
// ============================================================
template <bool RESID, bool TRANSOUT>
__global__ void gemm_bias_kernel(const float* __restrict__ A,
                                 const float* __restrict__ B,
                                 const float* __restrict__ bias,
                                 const float* __restrict__ R,
                                 float* __restrict__ C,
                                 int M, int N, int K)
{
    __shared__ float As[16][64];  // [k][m]
    __shared__ float Bs[16][64];  // [k][n]

    const int tid = threadIdx.x;
    const int tx = tid & 15;
    const int ty = tid >> 4;
    const int m0 = blockIdx.y * 64;
    const int n0 = blockIdx.x * 64;

    const int lr = tid >> 2;
    const int lc = (tid & 3) * 4;

    float acc[4][4] = {};

    for (int k0 = 0; k0 < K; k0 += 16) {
        float4 av = *(const float4*)&A[(size_t)(m0 + lr) * K + k0 + lc];
        float4 bv = *(const float4*)&B[(size_t)(n0 + lr) * K + k0 + lc];
        As[lc + 0][lr] = av.x; As[lc + 1][lr] = av.y;
        As[lc + 2][lr] = av.z; As[lc + 3][lr] = av.w;
        Bs[lc + 0][lr] = bv.x; Bs[lc + 1][lr] = bv.y;
        Bs[lc + 2][lr] = bv.z; Bs[lc + 3][lr] = bv.w;
        __syncthreads();

#pragma unroll
        for (int kk = 0; kk < 16; kk++) {
            float4 a4 = *(const float4*)&As[kk][ty * 4];
            float4 b4 = *(const float4*)&Bs[kk][tx * 4];
            float a[4] = {a4.x, a4.y, a4.z, a4.w};
            float b[4] = {b4.x, b4.y, b4.z, b4.w};
#pragma unroll
            for (int i = 0; i < 4; i++)
#pragma unroll
                for (int j = 0; j < 4; j++)
                    acc[i][j] = fmaf(a[i], b[j], acc[i][j]);
        }
        __syncthreads();
    }

#pragma unroll
    for (int i = 0; i < 4; i++) {
        int m = m0 + ty * 4 + i;
#pragma unroll
        for (int j = 0; j < 4; j++) {
            int n = n0 + tx * 4 + j;
            float v = acc[i][j] + bias[n];
            if (RESID) v += R[(size_t)m * N + n];
            if (TRANSOUT) C[(size_t)n * M + m] = v;
            else          C[(size_t)m * N + n] = v;
        }
    }
}

// ============================================================
// Fused flash attention with distance bias (fp32, vectorized LDS).
// grid: (NQ/64, NH), 256 threads, 3 CTAs/SM.
// Q, K come in pre-transposed [h*64+k][seq] layout.
// ============================================================
#define TC 64
#define STRD 68  // padded stride (floats), keeps 16B alignment

// dynamic smem: sQT[64][68] sKT[64][68] sV[64][68] sS[64][68] + coords/state
#define ATTN_SMEM_FLOATS (4 * 64 * STRD + 128 + 128 + 192)
#define ATTN_SMEM_BYTES (ATTN_SMEM_FLOATS * 4)

__global__ void __launch_bounds__(256, 3)
attn_kernel(const float* __restrict__ QpT,
            const float* __restrict__ KpT,
            const float* __restrict__ Vp,
            const float* __restrict__ qcoord,
            const float* __restrict__ ccoord,
            const float* __restrict__ log_scale,
            const float* __restrict__ bias_ph,
            float* __restrict__ ctx)
{
    extern __shared__ float sm[];
    float* sQT    = sm;                    // [k][r]
    float* sKT    = sQT + 64 * STRD;       // [k][c]
    float* sV     = sKT + 64 * STRD;       // [c][d]
    float* sS     = sV  + 64 * STRD;       // [r][c]
    float* sQC    = sS  + 64 * STRD;       // 128
    float* sCC    = sQC + 128;             // 128
    float* sM     = sCC + 128;
    float* sL     = sM + 64;
    float* sAlpha = sL + 64;

    const int h   = blockIdx.y;
    const int q0  = blockIdx.x * 64;
    const int tid = threadIdx.x;
    const int lane = tid & 31;
    const int wid  = tid >> 5;

    const float coef  = -__expf(log_scale[0]) * bias_ph[h];
    const float scale = 0.125f;  // 1/sqrt(64)

    // ---- load Q tile (transposed layout, coalesced) ----
    {
        int k  = tid >> 2;
        int r0 = (tid & 3) * 16;
        const float* src = &QpT[(size_t)(h * HD + k) * NQ + q0 + r0];
        float* dst = &sQT[k * STRD + r0];
#pragma unroll
        for (int i = 0; i < 16; i += 4)
            *(float4*)&dst[i] = *(const float4*)&src[i];
    }
    if (tid < 64) {
        sQC[tid * 2 + 0] = qcoord[(q0 + tid) * 2 + 0];
        sQC[tid * 2 + 1] = qcoord[(q0 + tid) * 2 + 1];
        sM[tid] = -INFINITY;
        sL[tid] = 0.0f;
        sAlpha[tid] = 1.0f;
    }
    __syncthreads();

    const int ty = tid >> 4;       // 0..15 (row group)
    const int tx = tid & 15;       // 0..15 (col group)
    const int orow = tid >> 2;     // 0..63
    const int od0  = (tid & 3) * 16;
    float o[16] = {};

    for (int c0 = 0; c0 < NC; c0 += TC) {
        // ---- load K tile (transposed layout, coalesced) + V tile ----
        {
            int k  = tid >> 2;
            int cl = (tid & 3) * 16;
            const float* src = &KpT[(size_t)(h * HD + k) * NC + c0 + cl];
            float* dst = &sKT[k * STRD + cl];
#pragma unroll
            for (int i = 0; i < 16; i += 4)
                *(float4*)&dst[i] = *(const float4*)&src[i];
        }
        {
            int c  = tid >> 2;
            int d0 = (tid & 3) * 16;
            const float* src = &Vp[(size_t)(c0 + c) * DIM + h * HD + d0];
            float* dst = &sV[c * STRD + d0];
#pragma unroll
            for (int i = 0; i < 16; i += 4)
                *(float4*)&dst[i] = *(const float4*)&src[i];
        }
        if (tid < 64) {
            sCC[tid * 2 + 0] = ccoord[(c0 + tid) * 2 + 0];
            sCC[tid * 2 + 1] = ccoord[(c0 + tid) * 2 + 1];
        }
        __syncthreads();

        // ---- scores: acc[i][j] = sum_k Q[r][k] K[c][k], vectorized LDS ----
        {
            float acc[4][4] = {};
#pragma unroll 16
            for (int k = 0; k < 64; k++) {
                float4 a4 = *(const float4*)&sQT[k * STRD + ty * 4];
                float4 b4 = *(const float4*)&sKT[k * STRD + tx * 4];
                float a[4] = {a4.x, a4.y, a4.z, a4.w};
                float b[4] = {b4.x, b4.y, b4.z, b4.w};
#pragma unroll
                for (int i = 0; i < 4; i++)
#pragma unroll
                    for (int j = 0; j < 4; j++)
                        acc[i][j] = fmaf(a[i], b[j], acc[i][j]);
            }
#pragma unroll
            for (int i = 0; i < 4; i++) {
                int r = ty * 4 + i;
                float qx = sQC[r * 2], qy = sQC[r * 2 + 1];
                float4 sv;
                float tmp[4];
#pragma unroll
                for (int j = 0; j < 4; j++) {
                    int c = tx * 4 + j;
                    float dx = qx - sCC[c * 2];
                    float dy = qy - sCC[c * 2 + 1];
                    float dist = sqrtf(dx * dx + dy * dy);
                    tmp[j] = fmaf(acc[i][j], scale, coef * dist);
                }
                sv.x = tmp[0]; sv.y = tmp[1]; sv.z = tmp[2]; sv.w = tmp[3];
                *(float4*)&sS[r * STRD + tx * 4] = sv;
            }
        }
        __syncthreads();

        // ---- online softmax: warp wid owns rows wid*8 .. wid*8+7 ----
        {
#pragma unroll
            for (int rr = 0; rr < 8; rr++) {
                int r = wid * 8 + rr;
                float s0 = sS[r * STRD + lane];
                float s1 = sS[r * STRD + lane + 32];
                float mx = fmaxf(s0, s1);
#pragma unroll
                for (int off = 16; off > 0; off >>= 1)
                    mx = fmaxf(mx, __shfl_xor_sync(0xffffffffu, mx, off));
                float m_old = sM[r];
                float m_new = fmaxf(m_old, mx);
                float p0 = __expf(s0 - m_new);
                float p1 = __expf(s1 - m_new);
                float ps = p0 + p1;
#pragma unroll
                for (int off = 16; off > 0; off >>= 1)
                    ps += __shfl_xor_sync(0xffffffffu, ps, off);
                sS[r * STRD + lane]      = p0;
                sS[r * STRD + lane + 32] = p1;
                if (lane == 0) {
                    float alpha = __expf(m_old - m_new);
                    sAlpha[r] = alpha;
                    sL[r] = sL[r] * alpha + ps;
                    sM[r] = m_new;
                }
            }
        }
        __syncthreads();

        // ---- O = O*alpha + P @ V, vectorized sV reads ----
        {
            float alpha = sAlpha[orow];
#pragma unroll
            for (int i = 0; i < 16; i++) o[i] *= alpha;
#pragma unroll 8
            for (int c = 0; c < TC; c++) {
                float p = sS[orow * STRD + c];
                const float* vr = &sV[c * STRD + od0];
                float4 v0 = *(const float4*)&vr[0];
                float4 v1 = *(const float4*)&vr[4];
                float4 v2 = *(const float4*)&vr[8];
                float4 v3 = *(const float4*)&vr[12];
                o[0]  = fmaf(p, v0.x, o[0]);  o[1]  = fmaf(p, v0.y, o[1]);
                o[2]  = fmaf(p, v0.z, o[2]);  o[3]  = fmaf(p, v0.w, o[3]);
                o[4]  = fmaf(p, v1.x, o[4]);  o[5]  = fmaf(p, v1.y, o[5]);
                o[6]  = fmaf(p, v1.z, o[6]);  o[7]  = fmaf(p, v1.w, o[7]);
                o[8]  = fmaf(p, v2.x, o[8]);  o[9]  = fmaf(p, v2.y, o[9]);
                o[10] = fmaf(p, v2.z, o[10]); o[11] = fmaf(p, v2.w, o[11]);
                o[12] = fmaf(p, v3.x, o[12]); o[13] = fmaf(p, v3.y, o[13]);
                o[14] = fmaf(p, v3.z, o[14]); o[15] = fmaf(p, v3.w, o[15]);
            }
        }
        __syncthreads();
    }

    // ---- normalize and write ----
    float rl = 1.0f / sL[orow];
    float* dst = &ctx[(size_t)(q0 + orow) * DIM + h * HD + od0];
#pragma unroll
    for (int i = 0; i < 16; i++) dst[i] = o[i] * rl;
}

// ============================================================
// LayerNorm: one block per row (512 dims), 128 threads x 4 elems
// ============================================================
__global__ void ln_kernel(const float* __restrict__ X,
                          const float* __restrict__ gam,
                          const float* __restrict__ bet,
                          float* __restrict__ out)
{
    __shared__ float red[32];
    const int row = blockIdx.x;
    const int tid = threadIdx.x;
    const float* x = &X[(size_t)row * DIM];

    float v[4];
    float s = 0.0f;
#pragma unroll
    for (int i = 0; i < 4; i++) {
        v[i] = x[tid + i * 128];
        s += v[i];
    }
#pragma unroll
    for (int off = 16; off > 0; off >>= 1)
        s += __shfl_xor_sync(0xffffffffu, s, off);
    if ((tid & 31) == 0) red[tid >> 5] = s;
    __syncthreads();
    if (tid < 32) {
        float t = (tid < 4) ? red[tid] : 0.0f;
#pragma unroll
        for (int off = 2; off > 0; off >>= 1)
            t += __shfl_xor_sync(0xffffffffu, t, off);
        if (tid == 0) red[0] = t;
    }
    __syncthreads();
    float mu = red[0] * (1.0f / DIM);

    float s2 = 0.0f;
#pragma unroll
    for (int i = 0; i < 4; i++) {
        float d = v[i] - mu;
        s2 += d * d;
    }
#pragma unroll
    for (int off = 16; off > 0; off >>= 1)
        s2 += __shfl_xor_sync(0xffffffffu, s2, off);
    __syncthreads();
    if ((tid & 31) == 0) red[tid >> 5] = s2;
    __syncthreads();
    if (tid < 32) {
        float t = (tid < 4) ? red[tid] : 0.0f;
#pragma unroll
        for (int off = 2; off > 0; off >>= 1)
            t += __shfl_xor_sync(0xffffffffu, t, off);
        if (tid == 0) red[0] = t;
    }
    __syncthreads();
    float rstd = rsqrtf(red[0] * (1.0f / DIM) + LN_EPS);

#pragma unroll
    for (int i = 0; i < 4; i++) {
        int c = tid + i * 128;
        out[(size_t)row * DIM + c] = (v[i] - mu) * rstd * gam[c] + bet[c];
    }
}

// ============================================================
extern "C" void kernel_launch(void* const* d_in, const int* in_sizes, int n_in,
                              void* d_out, int out_size)
{
    const float* query   = (const float*)d_in[0];
    const float* context = (const float*)d_in[1];
    const float* qcoord  = (const float*)d_in[2];
    const float* ccoord  = (const float*)d_in[3];
    const float* Wq = (const float*)d_in[4];
    const float* bq = (const float*)d_in[5];
    const float* Wk = (const float*)d_in[6];
    const float* bk = (const float*)d_in[7];
    const float* Wv = (const float*)d_in[8];
    const float* bv = (const float*)d_in[9];
    const float* Wo = (const float*)d_in[10];
    const float* bo = (const float*)d_in[11];
    const float* ln_g = (const float*)d_in[12];
    const float* ln_b = (const float*)d_in[13];
    const float* log_scale = (const float*)d_in[14];
    const float* bias_ph   = (const float*)d_in[15];
    float* out = (float*)d_out;

    float *QpT, *KpT, *Vp, *ctx, *x;
    cudaGetSymbolAddress((void**)&QpT, g_QpT);
    cudaGetSymbolAddress((void**)&KpT, g_KpT);
    cudaGetSymbolAddress((void**)&Vp,  g_Vp);
    cudaGetSymbolAddress((void**)&ctx, g_ctx);
    cudaGetSymbolAddress((void**)&x,   g_x);

    // projections (Q, K written transposed for the attention kernel)
    gemm_bias_kernel<false, true><<<dim3(DIM / 64, NQ / 64), 256>>>(
        query, Wq, bq, nullptr, QpT, NQ, DIM, DIM);
    gemm_bias_kernel<false, true><<<dim3(DIM / 64, NC / 64), 256>>>(
        context, Wk, bk, nullptr, KpT, NC, DIM, DIM);
    gemm_bias_kernel<false, false><<<dim3(DIM / 64, NC / 64), 256>>>(
        context, Wv, bv, nullptr, Vp, NC, DIM, DIM);

    // fused attention
    cudaFuncSetAttribute(attn_kernel,
                         cudaFuncAttributeMaxDynamicSharedMemorySize,
                         ATTN_SMEM_BYTES);
    attn_kernel<<<dim3(NQ / 64, NH), 256, ATTN_SMEM_BYTES>>>(
        QpT, KpT, Vp, qcoord, ccoord, log_scale, bias_ph, ctx);

    // output projection + residual
    gemm_bias_kernel<true, false><<<dim3(DIM / 64, NQ / 64), 256>>>(
        ctx, Wo, bo, query, x, NQ, DIM, DIM);

    // LayerNorm
    ln_kernel<<<NQ, 128>>>(x, ln_g, ln_b, out);
}

// round 5
// speedup vs baseline: 5.9560x; 4.7999x over previous
#include <cuda_runtime.h>
#include <cuda_bf16.h>
#include <math.h>
#include <stdint.h>

#define NQ 2048
#define NC 4096
#define DIM 512
#define NH 8
#define HD 64
#define LN_EPS 1e-5f

// ---------------- scratch ----------------
__device__ __nv_bfloat16 g_Qb[NQ * DIM];   // [q][h*64+k]
__device__ __nv_bfloat16 g_Kb[NC * DIM];   // [c][h*64+k]
__device__ __nv_bfloat16 g_Vb[NC * DIM];   // [c][h*64+d]
__device__ float g_ctx[NQ * DIM];
__device__ float g_x[NQ * DIM];

// ============================================================
// PTX helpers (all base-sm_103 legal: mma.sync / ldmatrix / cp.async)
// ============================================================
__device__ __forceinline__ uint32_t smem_u32(const void* p) {
    uint32_t a;
    asm("{ .reg .u64 t; cvta.to.shared.u64 t, %1; cvt.u32.u64 %0, t; }"
        : "=r"(a) : "l"(p));
    return a;
}
__device__ __forceinline__ float sqrt_approx(float x) {
    float y; asm("sqrt.approx.f32 %0, %1;" : "=f"(y) : "f"(x)); return y;
}
__device__ __forceinline__ uint32_t pack_bf16x2(float lo, float hi) {
    uint32_t r;
    asm("cvt.rn.bf16x2.f32 %0, %2, %1;" : "=r"(r) : "f"(lo), "f"(hi));
    return r;
}
__device__ __forceinline__ void ldsm_x4(uint32_t* r, uint32_t addr) {
    asm volatile("ldmatrix.sync.aligned.m8n8.x4.shared.b16 {%0,%1,%2,%3}, [%4];"
                 : "=r"(r[0]), "=r"(r[1]), "=r"(r[2]), "=r"(r[3]) : "r"(addr));
}
__device__ __forceinline__ void ldsm_x2(uint32_t* r, uint32_t addr) {
    asm volatile("ldmatrix.sync.aligned.m8n8.x2.shared.b16 {%0,%1}, [%2];"
                 : "=r"(r[0]), "=r"(r[1]) : "r"(addr));
}
__device__ __forceinline__ void ldsm_x2t(uint32_t* r, uint32_t addr) {
    asm volatile("ldmatrix.sync.aligned.m8n8.x2.trans.shared.b16 {%0,%1}, [%2];"
                 : "=r"(r[0]), "=r"(r[1]) : "r"(addr));
}
__device__ __forceinline__ void mma_bf16(float* c, const uint32_t* a, const uint32_t* b) {
    asm volatile(
        "mma.sync.aligned.m16n8k16.row.col.f32.bf16.bf16.f32 "
        "{%0,%1,%2,%3}, {%4,%5,%6,%7}, {%8,%9}, {%0,%1,%2,%3};"
        : "+f"(c[0]), "+f"(c[1]), "+f"(c[2]), "+f"(c[3])
        : "r"(a[0]), "r"(a[1]), "r"(a[2]), "r"(a[3]), "r"(b[0]), "r"(b[1]));
}
__device__ __forceinline__ void cp16(uint32_t s, const void* g) {
    asm volatile("cp.async.cg.shared.global [%0], [%1], 16;" :: "r"(s), "l"(g));
}
__device__ __forceinline__ void cp8(uint32_t s, const void* g) {
    asm volatile("cp.async.ca.shared.global [%0], [%1], 8;" :: "r"(s), "l"(g));
}
#define CP_COMMIT() asm volatile("cp.async.commit_group;" ::: "memory")
template <int N>
__device__ __forceinline__ void cp_wait() {
    asm volatile("cp.async.wait_group %0;" :: "n"(N) : "memory");
}

// ============================================================
// GEMM: C = A[M,K] @ B[N,K]^T + bias[N] (+residual)
// MODE 0: fp32 out; MODE 1: bf16 out (natural layout)
// ============================================================
template <bool RESID, int MODE>
__global__ void gemm_bias_kernel(const float* __restrict__ A,
                                 const float* __restrict__ B,
                                 const float* __restrict__ bias,
                                 const float* __restrict__ R,
                                 void* __restrict__ Cv,
                                 int M, int N, int K)
{
    __shared__ float As[16][64];
    __shared__ float Bs[16][64];

    const int tid = threadIdx.x;
    const int tx = tid & 15;
    const int ty = tid >> 4;
    const int m0 = blockIdx.y * 64;
    const int n0 = blockIdx.x * 64;
    const int lr = tid >> 2;
    const int lc = (tid & 3) * 4;

    float acc[4][4] = {};

    for (int k0 = 0; k0 < K; k0 += 16) {
        float4 av = *(const float4*)&A[(size_t)(m0 + lr) * K + k0 + lc];
        float4 bv = *(const float4*)&B[(size_t)(n0 + lr) * K + k0 + lc];
        As[lc + 0][lr] = av.x; As[lc + 1][lr] = av.y;
        As[lc + 2][lr] = av.z; As[lc + 3][lr] = av.w;
        Bs[lc + 0][lr] = bv.x; Bs[lc + 1][lr] = bv.y;
        Bs[lc + 2][lr] = bv.z; Bs[lc + 3][lr] = bv.w;
        __syncthreads();
#pragma unroll
        for (int kk = 0; kk < 16; kk++) {
            float4 a4 = *(const float4*)&As[kk][ty * 4];
            float4 b4 = *(const float4*)&Bs[kk][tx * 4];
            float a[4] = {a4.x, a4.y, a4.z, a4.w};
            float b[4] = {b4.x, b4.y, b4.z, b4.w};
#pragma unroll
            for (int i = 0; i < 4; i++)
#pragma unroll
                for (int j = 0; j < 4; j++)
                    acc[i][j] = fmaf(a[i], b[j], acc[i][j]);
        }
        __syncthreads();
    }

#pragma unroll
    for (int i = 0; i < 4; i++) {
        int m = m0 + ty * 4 + i;
#pragma unroll
        for (int j = 0; j < 4; j++) {
            int n = n0 + tx * 4 + j;
            float v = acc[i][j] + bias[n];
            if (RESID) v += R[(size_t)m * N + n];
            if (MODE == 0)
                ((float*)Cv)[(size_t)m * N + n] = v;
            else
                ((__nv_bfloat16*)Cv)[(size_t)m * N + n] = __float2bfloat16_rn(v);
        }
    }
}

// ============================================================
// Flash attention via mma.sync (bf16 HMMA), cp.async double buffer.
// CTA: 128 queries x 1 head, 8 warps (each owns 16 q rows), ctx tile 64.
// ============================================================
#define TCC 64
#define NT (NC / TCC)
#define RSTR 144   // smem row stride bytes (72 bf16) -> conflict-free ldmatrix

#define OFF_SQ  0                         // 128 * 144 = 18432
#define OFF_SK  18432                     // 2 bufs * 64*144
#define OFF_SV  (18432 + 18432)           // 2 bufs * 64*144
#define OFF_SCC (18432 + 36864)           // 2 bufs * 512
#define ATTN_SMEM (OFF_SCC + 1024 + 64)

__device__ __forceinline__ void prefetch_kv(uint32_t sbase,
                                            const __nv_bfloat16* __restrict__ Kb,
                                            const __nv_bfloat16* __restrict__ Vb,
                                            const float* __restrict__ ccoord,
                                            int h, int c0, int buf, int tid)
{
    uint32_t sk = sbase + OFF_SK + buf * 9216;
    uint32_t sv = sbase + OFF_SV + buf * 9216;
#pragma unroll
    for (int i = 0; i < 2; i++) {
        int idx = tid + i * 256;          // 0..511
        int row = idx >> 3, seg = idx & 7;
        const __nv_bfloat16* gk = Kb + (size_t)(c0 + row) * DIM + h * HD + seg * 8;
        const __nv_bfloat16* gv = Vb + (size_t)(c0 + row) * DIM + h * HD + seg * 8;
        cp16(sk + row * RSTR + seg * 16, gk);
        cp16(sv + row * RSTR + seg * 16, gv);
    }
    if (tid < TCC)
        cp8(sbase + OFF_SCC + buf * 512 + tid * 8, ccoord + (size_t)(c0 + tid) * 2);
}

__global__ void __launch_bounds__(256)
attn_mma_kernel(const __nv_bfloat16* __restrict__ Qb,
                const __nv_bfloat16* __restrict__ Kb,
                const __nv_bfloat16* __restrict__ Vb,
                const float* __restrict__ qcoord,
                const float* __restrict__ ccoord,
                const float* __restrict__ log_scale,
                const float* __restrict__ bias_ph,
                float* __restrict__ ctx)
{
    extern __shared__ char sb[];
    const uint32_t sbase = smem_u32(sb);

    const int tid  = threadIdx.x;
    const int w    = tid >> 5;
    const int lane = tid & 31;
    const int q0   = blockIdx.x * 128;
    const int h    = blockIdx.y;

    const float coef = -__expf(log_scale[0]) * bias_ph[h];

    // ---- stage Q tile into smem (rows 0..127, stride 144B) ----
#pragma unroll
    for (int i = 0; i < 4; i++) {
        int idx = tid + i * 256;          // 0..1023
        int row = idx >> 3, seg = idx & 7;
        float4 v = *(const float4*)(Qb + (size_t)(q0 + row) * DIM + h * HD + seg * 8);
        *(float4*)(sb + OFF_SQ + row * RSTR + seg * 16) = v;
    }
    prefetch_kv(sbase, Kb, Vb, ccoord, h, 0, 0, tid);
    CP_COMMIT();
    __syncthreads();

    // ---- per-thread resident Q fragments (4 k-steps) ----
    uint32_t qa[4][4];
#pragma unroll
    for (int kk = 0; kk < 4; kk++) {
        uint32_t addr = sbase + OFF_SQ + (w * 16 + (lane & 15)) * RSTR
                        + (kk * 16 + (lane >> 4) * 8) * 2;
        ldsm_x4(qa[kk], addr);
    }

    // query coords for this thread's two rows
    const int r0g = q0 + w * 16 + (lane >> 2);
    const float qx0 = qcoord[(size_t)r0g * 2 + 0];
    const float qy0 = qcoord[(size_t)r0g * 2 + 1];
    const float qx1 = qcoord[(size_t)(r0g + 8) * 2 + 0];
    const float qy1 = qcoord[(size_t)(r0g + 8) * 2 + 1];

    float o[8][4] = {};
    float m0 = -INFINITY, m1 = -INFINITY, l0 = 0.0f, l1 = 0.0f;

    for (int t = 0; t < NT; t++) {
        const int buf = t & 1;
        if (t + 1 < NT) {
            prefetch_kv(sbase, Kb, Vb, ccoord, h, (t + 1) * TCC, buf ^ 1, tid);
            CP_COMMIT();
            cp_wait<1>();
        } else {
            cp_wait<0>();
        }
        __syncthreads();

        const uint32_t skb = sbase + OFF_SK + buf * 9216;
        const uint32_t svb = sbase + OFF_SV + buf * 9216;

        // ---- S = Q @ K^T  (8 n-tiles x 4 k-steps) ----
        float s[8][4];
#pragma unroll
        for (int j = 0; j < 8; j++) { s[j][0] = s[j][1] = s[j][2] = s[j][3] = 0.0f; }
#pragma unroll
        for (int kk = 0; kk < 4; kk++) {
#pragma unroll
            for (int j = 0; j < 8; j++) {
                uint32_t kb[2];
                uint32_t addr = skb + (j * 8 + (lane & 7)) * RSTR
                                + (kk * 16 + ((lane >> 3) & 1) * 8) * 2;
                ldsm_x2(kb, addr);
                mma_bf16(s[j], qa[kk], kb);
            }
        }

        // ---- distance bias + online softmax ----
        const float2* ccb = (const float2*)(sb + OFF_SCC + buf * 512);
        float mx0 = -INFINITY, mx1 = -INFINITY;
#pragma unroll
        for (int j = 0; j < 8; j++) {
            int cb = j * 8 + 2 * (lane & 3);
            float2 ca = ccb[cb];
            float2 cbv = ccb[cb + 1];
            float dx, dy;
            dx = qx0 - ca.x;  dy = qy0 - ca.y;
            s[j][0] = fmaf(s[j][0], 0.125f, coef * sqrt_approx(fmaf(dx, dx, dy * dy)));
            dx = qx0 - cbv.x; dy = qy0 - cbv.y;
            s[j][1] = fmaf(s[j][1], 0.125f, coef * sqrt_approx(fmaf(dx, dx, dy * dy)));
            dx = qx1 - ca.x;  dy = qy1 - ca.y;
            s[j][2] = fmaf(s[j][2], 0.125f, coef * sqrt_approx(fmaf(dx, dx, dy * dy)));
            dx = qx1 - cbv.x; dy = qy1 - cbv.y;
            s[j][3] = fmaf(s[j][3], 0.125f, coef * sqrt_approx(fmaf(dx, dx, dy * dy)));
            mx0 = fmaxf(mx0, fmaxf(s[j][0], s[j][1]));
            mx1 = fmaxf(mx1, fmaxf(s[j][2], s[j][3]));
        }
        mx0 = fmaxf(mx0, __shfl_xor_sync(0xffffffffu, mx0, 1));
        mx0 = fmaxf(mx0, __shfl_xor_sync(0xffffffffu, mx0, 2));
        mx1 = fmaxf(mx1, __shfl_xor_sync(0xffffffffu, mx1, 1));
        mx1 = fmaxf(mx1, __shfl_xor_sync(0xffffffffu, mx1, 2));

        float mn0 = fmaxf(m0, mx0), mn1 = fmaxf(m1, mx1);
        float a0 = __expf(m0 - mn0), a1 = __expf(m1 - mn1);
        m0 = mn0; m1 = mn1;

        float sum0 = 0.0f, sum1 = 0.0f;
#pragma unroll
        for (int j = 0; j < 8; j++) {
            s[j][0] = __expf(s[j][0] - mn0);
            s[j][1] = __expf(s[j][1] - mn0);
            s[j][2] = __expf(s[j][2] - mn1);
            s[j][3] = __expf(s[j][3] - mn1);
            sum0 += s[j][0] + s[j][1];
            sum1 += s[j][2] + s[j][3];
        }
        sum0 += __shfl_xor_sync(0xffffffffu, sum0, 1);
        sum0 += __shfl_xor_sync(0xffffffffu, sum0, 2);
        sum1 += __shfl_xor_sync(0xffffffffu, sum1, 1);
        sum1 += __shfl_xor_sync(0xffffffffu, sum1, 2);
        l0 = l0 * a0 + sum0;
        l1 = l1 * a1 + sum1;

        // ---- rescale O ----
#pragma unroll
        for (int j = 0; j < 8; j++) {
            o[j][0] *= a0; o[j][1] *= a0; o[j][2] *= a1; o[j][3] *= a1;
        }

        // ---- P fragments (bf16) ----
        uint32_t pf[4][4];
#pragma unroll
        for (int kk = 0; kk < 4; kk++) {
            pf[kk][0] = pack_bf16x2(s[2 * kk][0],     s[2 * kk][1]);
            pf[kk][1] = pack_bf16x2(s[2 * kk][2],     s[2 * kk][3]);
            pf[kk][2] = pack_bf16x2(s[2 * kk + 1][0], s[2 * kk + 1][1]);
            pf[kk][3] = pack_bf16x2(s[2 * kk + 1][2], s[2 * kk + 1][3]);
        }

        // ---- O += P @ V  (8 d-tiles x 4 k-steps) ----
#pragma unroll
        for (int kk = 0; kk < 4; kk++) {
#pragma unroll
            for (int j = 0; j < 8; j++) {
                uint32_t vb[2];
                uint32_t addr = svb + (kk * 16 + (lane & 7) + ((lane >> 3) & 1) * 8) * RSTR
                                + j * 16;
                ldsm_x2t(vb, addr);
                mma_bf16(o[j], pf[kk], vb);
            }
        }
        __syncthreads();   // all warps done with buf before it is overwritten
    }

    // ---- normalize and write ----
    float rl0 = 1.0f / l0, rl1 = 1.0f / l1;
#pragma unroll
    for (int j = 0; j < 8; j++) {
        int col = h * HD + j * 8 + 2 * (lane & 3);
        float2 v0 = make_float2(o[j][0] * rl0, o[j][1] * rl0);
        float2 v1 = make_float2(o[j][2] * rl1, o[j][3] * rl1);
        *(float2*)&ctx[(size_t)r0g * DIM + col] = v0;
        *(float2*)&ctx[(size_t)(r0g + 8) * DIM + col] = v1;
    }
}

// ============================================================
// LayerNorm
// ============================================================
__global__ void ln_kernel(const float* __restrict__ X,
                          const float* __restrict__ gam,
                          const float* __restrict__ bet,
                          float* __restrict__ out)
{
    __shared__ float red[32];
    const int row = blockIdx.x;
    const int tid = threadIdx.x;
    const float* x = &X[(size_t)row * DIM];

    float v[4];
    float s = 0.0f;
#pragma unroll
    for (int i = 0; i < 4; i++) { v[i] = x[tid + i * 128]; s += v[i]; }
#pragma unroll
    for (int off = 16; off > 0; off >>= 1)
        s += __shfl_xor_sync(0xffffffffu, s, off);
    if ((tid & 31) == 0) red[tid >> 5] = s;
    __syncthreads();
    if (tid < 32) {
        float t = (tid < 4) ? red[tid] : 0.0f;
#pragma unroll
        for (int off = 2; off > 0; off >>= 1)
            t += __shfl_xor_sync(0xffffffffu, t, off);
        if (tid == 0) red[0] = t;
    }
    __syncthreads();
    float mu = red[0] * (1.0f / DIM);

    float s2 = 0.0f;
#pragma unroll
    for (int i = 0; i < 4; i++) { float d = v[i] - mu; s2 += d * d; }
#pragma unroll
    for (int off = 16; off > 0; off >>= 1)
        s2 += __shfl_xor_sync(0xffffffffu, s2, off);
    __syncthreads();
    if ((tid & 31) == 0) red[tid >> 5] = s2;
    __syncthreads();
    if (tid < 32) {
        float t = (tid < 4) ? red[tid] : 0.0f;
#pragma unroll
        for (int off = 2; off > 0; off >>= 1)
            t += __shfl_xor_sync(0xffffffffu, t, off);
        if (tid == 0) red[0] = t;
    }
    __syncthreads();
    float rstd = rsqrtf(red[0] * (1.0f / DIM) + LN_EPS);
#pragma unroll
    for (int i = 0; i < 4; i++) {
        int c = tid + i * 128;
        out[(size_t)row * DIM + c] = (v[i] - mu) * rstd * gam[c] + bet[c];
    }
}

// ============================================================
extern "C" void kernel_launch(void* const* d_in, const int* in_sizes, int n_in,
                              void* d_out, int out_size)
{
    const float* query   = (const float*)d_in[0];
    const float* context = (const float*)d_in[1];
    const float* qcoord  = (const float*)d_in[2];
    const float* ccoord  = (const float*)d_in[3];
    const float* Wq = (const float*)d_in[4];
    const float* bq = (const float*)d_in[5];
    const float* Wk = (const float*)d_in[6];
    const float* bk = (const float*)d_in[7];
    const float* Wv = (const float*)d_in[8];
    const float* bv = (const float*)d_in[9];
    const float* Wo = (const float*)d_in[10];
    const float* bo = (const float*)d_in[11];
    const float* ln_g = (const float*)d_in[12];
    const float* ln_b = (const float*)d_in[13];
    const float* log_scale = (const float*)d_in[14];
    const float* bias_ph   = (const float*)d_in[15];
    float* out = (float*)d_out;

    __nv_bfloat16 *Qb, *Kb, *Vb;
    float *ctx, *x;
    cudaGetSymbolAddress((void**)&Qb,  g_Qb);
    cudaGetSymbolAddress((void**)&Kb,  g_Kb);
    cudaGetSymbolAddress((void**)&Vb,  g_Vb);
    cudaGetSymbolAddress((void**)&ctx, g_ctx);
    cudaGetSymbolAddress((void**)&x,   g_x);

    // projections -> bf16 (natural layouts)
    gemm_bias_kernel<false, 1><<<dim3(DIM / 64, NQ / 64), 256>>>(
        query, Wq, bq, nullptr, Qb, NQ, DIM, DIM);
    gemm_bias_kernel<false, 1><<<dim3(DIM / 64, NC / 64), 256>>>(
        context, Wk, bk, nullptr, Kb, NC, DIM, DIM);
    gemm_bias_kernel<false, 1><<<dim3(DIM / 64, NC / 64), 256>>>(
        context, Wv, bv, nullptr, Vb, NC, DIM, DIM);

    // mma.sync flash attention
    cudaFuncSetAttribute(attn_mma_kernel,
                         cudaFuncAttributeMaxDynamicSharedMemorySize, ATTN_SMEM);
    attn_mma_kernel<<<dim3(NQ / 128, NH), 256, ATTN_SMEM>>>(
        Qb, Kb, Vb, qcoord, ccoord, log_scale, bias_ph, ctx);

    // output projection + residual (fp32)
    gemm_bias_kernel<true, 0><<<dim3(DIM / 64, NQ / 64), 256>>>(
        ctx, Wo, bo, query, x, NQ, DIM, DIM);

    // LayerNorm
    ln_kernel<<<NQ, 128>>>(x, ln_g, ln_b, out);
}

// round 6
// speedup vs baseline: 15.1441x; 2.5427x over previous
#include <cuda_runtime.h>
#include <cuda_bf16.h>
#include <math.h>
#include <stdint.h>

#define NQ 2048
#define NC 4096
#define DIM 512
#define NH 8
#define HD 64
#define LN_EPS 1e-5f

// ---------------- scratch ----------------
__device__ __nv_bfloat16 g_qin[NQ * DIM];    // query bf16
__device__ __nv_bfloat16 g_cin[NC * DIM];    // context bf16
__device__ __nv_bfloat16 g_Wqb[DIM * DIM];
__device__ __nv_bfloat16 g_Wkb[DIM * DIM];
__device__ __nv_bfloat16 g_Wvb[DIM * DIM];
__device__ __nv_bfloat16 g_Wob[DIM * DIM];
__device__ __nv_bfloat16 g_Qb[NQ * DIM];
__device__ __nv_bfloat16 g_Kb[NC * DIM];
__device__ __nv_bfloat16 g_Vb[NC * DIM];
__device__ float g_po[2 * NQ * DIM];         // partial O (per ctx-split)
__device__ float g_pm[2 * NH * NQ];          // partial max
__device__ float g_pl[2 * NH * NQ];          // partial sum
__device__ __nv_bfloat16 g_ctxb[NQ * DIM];   // merged attention output
__device__ float g_x[NQ * DIM];              // pre-LN

// ============================================================
// PTX helpers (base sm_103 legal)
// ============================================================
__device__ __forceinline__ uint32_t smem_u32(const void* p) {
    uint32_t a;
    asm("{ .reg .u64 t; cvta.to.shared.u64 t, %1; cvt.u32.u64 %0, t; }"
        : "=r"(a) : "l"(p));
    return a;
}
__device__ __forceinline__ float sqrt_approx(float x) {
    float y; asm("sqrt.approx.f32 %0, %1;" : "=f"(y) : "f"(x)); return y;
}
__device__ __forceinline__ uint32_t pack_bf16x2(float lo, float hi) {
    uint32_t r;
    asm("cvt.rn.bf16x2.f32 %0, %2, %1;" : "=r"(r) : "f"(lo), "f"(hi));
    return r;
}
__device__ __forceinline__ void ldsm_x4(uint32_t* r, uint32_t addr) {
    asm volatile("ldmatrix.sync.aligned.m8n8.x4.shared.b16 {%0,%1,%2,%3}, [%4];"
                 : "=r"(r[0]), "=r"(r[1]), "=r"(r[2]), "=r"(r[3]) : "r"(addr));
}
__device__ __forceinline__ void ldsm_x2(uint32_t* r, uint32_t addr) {
    asm volatile("ldmatrix.sync.aligned.m8n8.x2.shared.b16 {%0,%1}, [%2];"
                 : "=r"(r[0]), "=r"(r[1]) : "r"(addr));
}
__device__ __forceinline__ void ldsm_x2t(uint32_t* r, uint32_t addr) {
    asm volatile("ldmatrix.sync.aligned.m8n8.x2.trans.shared.b16 {%0,%1}, [%2];"
                 : "=r"(r[0]), "=r"(r[1]) : "r"(addr));
}
__device__ __forceinline__ void mma_bf16(float* c, const uint32_t* a, const uint32_t* b) {
    asm volatile(
        "mma.sync.aligned.m16n8k16.row.col.f32.bf16.bf16.f32 "
        "{%0,%1,%2,%3}, {%4,%5,%6,%7}, {%8,%9}, {%0,%1,%2,%3};"
        : "+f"(c[0]), "+f"(c[1]), "+f"(c[2]), "+f"(c[3])
        : "r"(a[0]), "r"(a[1]), "r"(a[2]), "r"(a[3]), "r"(b[0]), "r"(b[1]));
}
__device__ __forceinline__ void cp16(uint32_t s, const void* g) {
    asm volatile("cp.async.cg.shared.global [%0], [%1], 16;" :: "r"(s), "l"(g));
}
__device__ __forceinline__ void cp8(uint32_t s, const void* g) {
    asm volatile("cp.async.ca.shared.global [%0], [%1], 8;" :: "r"(s), "l"(g));
}
#define CP_COMMIT() asm volatile("cp.async.commit_group;" ::: "memory")
template <int N>
__device__ __forceinline__ void cp_wait() {
    asm volatile("cp.async.wait_group %0;" :: "n"(N) : "memory");
}

// ============================================================
// fp32 -> bf16 conversion kernels
// ============================================================
__global__ void conv_in2(const float* __restrict__ q, const float* __restrict__ c,
                         __nv_bfloat16* __restrict__ qo, __nv_bfloat16* __restrict__ co)
{
    int i = blockIdx.x * 256 + threadIdx.x;    // 0..786431 float4s
    const float* s; __nv_bfloat16* d; int off;
    if (i < (NQ * DIM / 4)) { s = q; d = qo; off = i; }
    else { s = c; d = co; off = i - NQ * DIM / 4; }
    float4 v = ((const float4*)s)[off];
    uint32_t* dst = (uint32_t*)d + (size_t)off * 2;
    dst[0] = pack_bf16x2(v.x, v.y);
    dst[1] = pack_bf16x2(v.z, v.w);
}

__global__ void conv_w4(const float* __restrict__ w0, const float* __restrict__ w1,
                        const float* __restrict__ w2, const float* __restrict__ w3,
                        __nv_bfloat16* __restrict__ d0, __nv_bfloat16* __restrict__ d1,
                        __nv_bfloat16* __restrict__ d2, __nv_bfloat16* __restrict__ d3)
{
    int i = blockIdx.x * 256 + threadIdx.x;    // 0..262143 float4s (4 x 65536)
    int sel = i >> 16, off = i & 65535;
    const float* s = sel == 0 ? w0 : sel == 1 ? w1 : sel == 2 ? w2 : w3;
    __nv_bfloat16* d = sel == 0 ? d0 : sel == 1 ? d1 : sel == 2 ? d2 : d3;
    float4 v = ((const float4*)s)[off];
    uint32_t* dst = (uint32_t*)d + (size_t)off * 2;
    dst[0] = pack_bf16x2(v.x, v.y);
    dst[1] = pack_bf16x2(v.z, v.w);
}

// ============================================================
// bf16 tensor-core GEMM: C[M,512] = A[M,512] @ W[512,512]^T + bias (+R fp32)
// CTA tile 128x128, BK=32, 8 warps (4m x 2n), cp.async double buffer.
// ============================================================
#define GSTR 80   // smem row stride bytes (32 bf16 data + pad)

template <bool RESID, bool OUTF32>
__device__ __forceinline__ void gemm_cta_128x128(
    const __nv_bfloat16* __restrict__ A,
    const __nv_bfloat16* __restrict__ W,
    const float* __restrict__ bias,
    const float* __restrict__ R,
    void* __restrict__ C,
    int m0, int n0, char* smem)
{
    const int tid = threadIdx.x;
    const int lane = tid & 31, w = tid >> 5;
    const int wm = w & 3, wn = w >> 2;
    const uint32_t sb = smem_u32(smem);

    float c[2][8][4] = {};

#define GLOAD(IT, BUF)                                                          \
    {                                                                           \
        uint32_t sa = sb + (BUF) * 20480;                                       \
        uint32_t sw = sa + 10240;                                               \
        int k0 = (IT) * 32;                                                     \
        _Pragma("unroll")                                                       \
        for (int i = 0; i < 2; i++) {                                           \
            int idx = tid + i * 256;                                            \
            int r = idx >> 2, seg = idx & 3;                                    \
            cp16(sa + r * GSTR + seg * 16,                                      \
                 A + (size_t)(m0 + r) * 512 + k0 + seg * 8);                    \
            cp16(sw + r * GSTR + seg * 16,                                      \
                 W + (size_t)(n0 + r) * 512 + k0 + seg * 8);                    \
        }                                                                       \
    }

    GLOAD(0, 0); CP_COMMIT();

    for (int it = 0; it < 16; it++) {
        if (it < 15) { GLOAD(it + 1, (it + 1) & 1); CP_COMMIT(); cp_wait<1>(); }
        else cp_wait<0>();
        __syncthreads();

        uint32_t sa = sb + (it & 1) * 20480;
        uint32_t sw = sa + 10240;
#pragma unroll
        for (int kk = 0; kk < 2; kk++) {
            uint32_t af[2][4];
#pragma unroll
            for (int mt = 0; mt < 2; mt++) {
                uint32_t addr = sa + (wm * 32 + mt * 16 + (lane & 15)) * GSTR
                                + kk * 32 + (lane >> 4) * 16;
                ldsm_x4(af[mt], addr);
            }
#pragma unroll
            for (int jp = 0; jp < 4; jp++) {
                uint32_t bf[4];
                uint32_t addr = sw + (wn * 64 + jp * 16 + ((lane >> 4) & 1) * 8 + (lane & 7)) * GSTR
                                + kk * 32 + ((lane >> 3) & 1) * 16;
                ldsm_x4(bf, addr);
#pragma unroll
                for (int mt = 0; mt < 2; mt++) {
                    mma_bf16(c[mt][2 * jp],     af[mt], bf);
                    mma_bf16(c[mt][2 * jp + 1], af[mt], bf + 2);
                }
            }
        }
        __syncthreads();
    }
#undef GLOAD

    // ---- epilogue ----
#pragma unroll
    for (int mt = 0; mt < 2; mt++) {
        int mr = m0 + wm * 32 + mt * 16 + (lane >> 2);
#pragma unroll
        for (int j = 0; j < 8; j++) {
            int nc = n0 + wn * 64 + j * 8 + (lane & 3) * 2;
            float2 bb = *(const float2*)&bias[nc];
            float v0 = c[mt][j][0] + bb.x, v1 = c[mt][j][1] + bb.y;
            float v2 = c[mt][j][2] + bb.x, v3 = c[mt][j][3] + bb.y;
            if (RESID) {
                float2 r0 = *(const float2*)&R[(size_t)mr * 512 + nc];
                float2 r1 = *(const float2*)&R[(size_t)(mr + 8) * 512 + nc];
                v0 += r0.x; v1 += r0.y; v2 += r1.x; v3 += r1.y;
            }
            if (OUTF32) {
                *(float2*)((float*)C + (size_t)mr * 512 + nc) = make_float2(v0, v1);
                *(float2*)((float*)C + (size_t)(mr + 8) * 512 + nc) = make_float2(v2, v3);
            } else {
                *(uint32_t*)((__nv_bfloat16*)C + (size_t)mr * 512 + nc) = pack_bf16x2(v0, v1);
                *(uint32_t*)((__nv_bfloat16*)C + (size_t)(mr + 8) * 512 + nc) = pack_bf16x2(v2, v3);
            }
        }
    }
}

// Fused QKV projections: grid (4, 32, 3); z selects op, early-exit beyond M.
__global__ void __launch_bounds__(256, 2)
qkv_mma_kernel(const __nv_bfloat16* __restrict__ qin,
               const __nv_bfloat16* __restrict__ cin,
               const __nv_bfloat16* __restrict__ Wq, const float* __restrict__ bq,
               const __nv_bfloat16* __restrict__ Wk, const float* __restrict__ bk,
               const __nv_bfloat16* __restrict__ Wv, const float* __restrict__ bv,
               __nv_bfloat16* __restrict__ Qb,
               __nv_bfloat16* __restrict__ Kb,
               __nv_bfloat16* __restrict__ Vb)
{
    __shared__ char smem[40960];
    const int z = blockIdx.z;
    const __nv_bfloat16* A; const __nv_bfloat16* W; const float* bias;
    __nv_bfloat16* C; int M;
    if (z == 0)      { A = qin; W = Wq; bias = bq; C = Qb; M = NQ; }
    else if (z == 1) { A = cin; W = Wk; bias = bk; C = Kb; M = NC; }
    else             { A = cin; W = Wv; bias = bv; C = Vb; M = NC; }
    int m0 = blockIdx.y * 128;
    if (m0 >= M) return;
    int n0 = blockIdx.x * 128;
    gemm_cta_128x128<false, false>(A, W, bias, nullptr, C, m0, n0, smem);
}

// O-projection + residual: grid (4, 16)
__global__ void __launch_bounds__(256, 2)
oproj_mma_kernel(const __nv_bfloat16* __restrict__ ctxb,
                 const __nv_bfloat16* __restrict__ Wo, const float* __restrict__ bo,
                 const float* __restrict__ query,
                 float* __restrict__ x)
{
    __shared__ char smem[40960];
    gemm_cta_128x128<true, true>(ctxb, Wo, bo, query, x,
                                 blockIdx.y * 128, blockIdx.x * 128, smem);
}

// ============================================================
// Flash attention via mma.sync, context split in 2 for occupancy.
// grid (16, 8, 2), 256 threads, 2 CTAs/SM. Each CTA: 128 q x 1 head x NC/2.
// ============================================================
#define TCC 64
#define NTT (NC / 2 / TCC)   // 32 tiles per split
#define RSTR 144

#define OFF_SQ  0
#define OFF_SK  18432
#define OFF_SV  (18432 + 18432)
#define OFF_SCC (18432 + 36864)
#define ATTN_SMEM (OFF_SCC + 1024 + 64)

__device__ __forceinline__ void prefetch_kv(uint32_t sbase,
                                            const __nv_bfloat16* __restrict__ Kb,
                                            const __nv_bfloat16* __restrict__ Vb,
                                            const float* __restrict__ ccoord,
                                            int h, int c0, int buf, int tid)
{
    uint32_t sk = sbase + OFF_SK + buf * 9216;
    uint32_t sv = sbase + OFF_SV + buf * 9216;
#pragma unroll
    for (int i = 0; i < 2; i++) {
        int idx = tid + i * 256;
        int row = idx >> 3, seg = idx & 7;
        cp16(sk + row * RSTR + seg * 16, Kb + (size_t)(c0 + row) * DIM + h * HD + seg * 8);
        cp16(sv + row * RSTR + seg * 16, Vb + (size_t)(c0 + row) * DIM + h * HD + seg * 8);
    }
    if (tid < TCC)
        cp8(sbase + OFF_SCC + buf * 512 + tid * 8, ccoord + (size_t)(c0 + tid) * 2);
}

__global__ void __launch_bounds__(256, 2)
attn_mma_kernel(const __nv_bfloat16* __restrict__ Qb,
                const __nv_bfloat16* __restrict__ Kb,
                const __nv_bfloat16* __restrict__ Vb,
                const float* __restrict__ qcoord,
                const float* __restrict__ ccoord,
                const float* __restrict__ log_scale,
                const float* __restrict__ bias_ph,
                float* __restrict__ po,
                float* __restrict__ pm,
                float* __restrict__ pl)
{
    extern __shared__ char sb[];
    const uint32_t sbase = smem_u32(sb);

    const int tid  = threadIdx.x;
    const int w    = tid >> 5;
    const int lane = tid & 31;
    const int q0   = blockIdx.x * 128;
    const int h    = blockIdx.y;
    const int cs   = blockIdx.z;
    const int cbase = cs * (NC / 2);

    const float coef = -__expf(log_scale[0]) * bias_ph[h];

    // stage Q tile
#pragma unroll
    for (int i = 0; i < 4; i++) {
        int idx = tid + i * 256;
        int row = idx >> 3, seg = idx & 7;
        float4 v = *(const float4*)(Qb + (size_t)(q0 + row) * DIM + h * HD + seg * 8);
        *(float4*)(sb + OFF_SQ + row * RSTR + seg * 16) = v;
    }
    prefetch_kv(sbase, Kb, Vb, ccoord, h, cbase, 0, tid);
    CP_COMMIT();
    __syncthreads();

    uint32_t qa[4][4];
#pragma unroll
    for (int kk = 0; kk < 4; kk++) {
        uint32_t addr = sbase + OFF_SQ + (w * 16 + (lane & 15)) * RSTR
                        + (kk * 16 + (lane >> 4) * 8) * 2;
        ldsm_x4(qa[kk], addr);
    }

    const int r0g = q0 + w * 16 + (lane >> 2);
    const float qx0 = qcoord[(size_t)r0g * 2 + 0];
    const float qy0 = qcoord[(size_t)r0g * 2 + 1];
    const float qx1 = qcoord[(size_t)(r0g + 8) * 2 + 0];
    const float qy1 = qcoord[(size_t)(r0g + 8) * 2 + 1];

    float o[8][4] = {};
    float m0 = -INFINITY, m1 = -INFINITY, l0 = 0.0f, l1 = 0.0f;

    for (int t = 0; t < NTT; t++) {
        const int buf = t & 1;
        if (t + 1 < NTT) {
            prefetch_kv(sbase, Kb, Vb, ccoord, h, cbase + (t + 1) * TCC, buf ^ 1, tid);
            CP_COMMIT();
            cp_wait<1>();
        } else {
            cp_wait<0>();
        }
        __syncthreads();

        const uint32_t skb = sbase + OFF_SK + buf * 9216;
        const uint32_t svb = sbase + OFF_SV + buf * 9216;

        float s[8][4];
#pragma unroll
        for (int j = 0; j < 8; j++) { s[j][0] = s[j][1] = s[j][2] = s[j][3] = 0.0f; }
#pragma unroll
        for (int kk = 0; kk < 4; kk++) {
#pragma unroll
            for (int j = 0; j < 8; j++) {
                uint32_t kb2[2];
                uint32_t addr = skb + (j * 8 + (lane & 7)) * RSTR
                                + (kk * 16 + ((lane >> 3) & 1) * 8) * 2;
                ldsm_x2(kb2, addr);
                mma_bf16(s[j], qa[kk], kb2);
            }
        }

        const float2* ccb = (const float2*)(sb + OFF_SCC + buf * 512);
        float mx0 = -INFINITY, mx1 = -INFINITY;
#pragma unroll
        for (int j = 0; j < 8; j++) {
            int cb = j * 8 + 2 * (lane & 3);
            float2 ca = ccb[cb];
            float2 cbv = ccb[cb + 1];
            float dx, dy;
            dx = qx0 - ca.x;  dy = qy0 - ca.y;
            s[j][0] = fmaf(s[j][0], 0.125f, coef * sqrt_approx(fmaf(dx, dx, dy * dy)));
            dx = qx0 - cbv.x; dy = qy0 - cbv.y;
            s[j][1] = fmaf(s[j][1], 0.125f, coef * sqrt_approx(fmaf(dx, dx, dy * dy)));
            dx = qx1 - ca.x;  dy = qy1 - ca.y;
            s[j][2] = fmaf(s[j][2], 0.125f, coef * sqrt_approx(fmaf(dx, dx, dy * dy)));
            dx = qx1 - cbv.x; dy = qy1 - cbv.y;
            s[j][3] = fmaf(s[j][3], 0.125f, coef * sqrt_approx(fmaf(dx, dx, dy * dy)));
            mx0 = fmaxf(mx0, fmaxf(s[j][0], s[j][1]));
            mx1 = fmaxf(mx1, fmaxf(s[j][2], s[j][3]));
        }
        mx0 = fmaxf(mx0, __shfl_xor_sync(0xffffffffu, mx0, 1));
        mx0 = fmaxf(mx0, __shfl_xor_sync(0xffffffffu, mx0, 2));
        mx1 = fmaxf(mx1, __shfl_xor_sync(0xffffffffu, mx1, 1));
        mx1 = fmaxf(mx1, __shfl_xor_sync(0xffffffffu, mx1, 2));

        float mn0 = fmaxf(m0, mx0), mn1 = fmaxf(m1, mx1);
        float a0 = __expf(m0 - mn0), a1 = __expf(m1 - mn1);
        m0 = mn0; m1 = mn1;

        float sum0 = 0.0f, sum1 = 0.0f;
#pragma unroll
        for (int j = 0; j < 8; j++) {
            s[j][0] = __expf(s[j][0] - mn0);
            s[j][1] = __expf(s[j][1] - mn0);
            s[j][2] = __expf(s[j][2] - mn1);
            s[j][3] = __expf(s[j][3] - mn1);
            sum0 += s[j][0] + s[j][1];
            sum1 += s[j][2] + s[j][3];
        }
        sum0 += __shfl_xor_sync(0xffffffffu, sum0, 1);
        sum0 += __shfl_xor_sync(0xffffffffu, sum0, 2);
        sum1 += __shfl_xor_sync(0xffffffffu, sum1, 1);
        sum1 += __shfl_xor_sync(0xffffffffu, sum1, 2);
        l0 = l0 * a0 + sum0;
        l1 = l1 * a1 + sum1;

#pragma unroll
        for (int j = 0; j < 8; j++) {
            o[j][0] *= a0; o[j][1] *= a0; o[j][2] *= a1; o[j][3] *= a1;
        }

        uint32_t pf[4][4];
#pragma unroll
        for (int kk = 0; kk < 4; kk++) {
            pf[kk][0] = pack_bf16x2(s[2 * kk][0],     s[2 * kk][1]);
            pf[kk][1] = pack_bf16x2(s[2 * kk][2],     s[2 * kk][3]);
            pf[kk][2] = pack_bf16x2(s[2 * kk + 1][0], s[2 * kk + 1][1]);
            pf[kk][3] = pack_bf16x2(s[2 * kk + 1][2], s[2 * kk + 1][3]);
        }

#pragma unroll
        for (int kk = 0; kk < 4; kk++) {
#pragma unroll
            for (int j = 0; j < 8; j++) {
                uint32_t vb2[2];
                uint32_t addr = svb + (kk * 16 + (lane & 7) + ((lane >> 3) & 1) * 8) * RSTR
                                + j * 16;
                ldsm_x2t(vb2, addr);
                mma_bf16(o[j], pf[kk], vb2);
            }
        }
        __syncthreads();
    }

    // ---- write partials (unnormalized) ----
    float* p0 = po + ((size_t)cs * NQ + r0g) * DIM + h * HD;
    float* p1 = po + ((size_t)cs * NQ + r0g + 8) * DIM + h * HD;
#pragma unroll
    for (int j = 0; j < 8; j++) {
        int col = j * 8 + 2 * (lane & 3);
        *(float2*)&p0[col] = make_float2(o[j][0], o[j][1]);
        *(float2*)&p1[col] = make_float2(o[j][2], o[j][3]);
    }
    if ((lane & 3) == 0) {
        size_t base = (size_t)(cs * NH + h) * NQ;
        pm[base + r0g] = m0;     pl[base + r0g] = l0;
        pm[base + r0g + 8] = m1; pl[base + r0g + 8] = l1;
    }
}

// ============================================================
// merge the 2 context splits -> bf16 ctx
// ============================================================
__global__ void merge_kernel(const float* __restrict__ po,
                             const float* __restrict__ pm,
                             const float* __restrict__ pl,
                             __nv_bfloat16* __restrict__ ctxb)
{
    const int q = blockIdx.x;
    const int t = threadIdx.x;         // 256 threads, 2 dims each
    const int d0 = t * 2;
    const int h = d0 >> 6;

    float m0 = pm[(size_t)h * NQ + q];
    float m1 = pm[(size_t)(NH + h) * NQ + q];
    float l0 = pl[(size_t)h * NQ + q];
    float l1 = pl[(size_t)(NH + h) * NQ + q];
    float m = fmaxf(m0, m1);
    float a0 = __expf(m0 - m), a1 = __expf(m1 - m);
    float rl = 1.0f / (l0 * a0 + l1 * a1);
    float w0 = a0 * rl, w1 = a1 * rl;

    float2 v0 = *(const float2*)&po[(size_t)q * DIM + d0];
    float2 v1 = *(const float2*)&po[(size_t)(NQ + q) * DIM + d0];
    *(uint32_t*)&ctxb[(size_t)q * DIM + d0] =
        pack_bf16x2(w0 * v0.x + w1 * v1.x, w0 * v0.y + w1 * v1.y);
}

// ============================================================
// LayerNorm
// ============================================================
__global__ void ln_kernel(const float* __restrict__ X,
                          const float* __restrict__ gam,
                          const float* __restrict__ bet,
                          float* __restrict__ out)
{
    __shared__ float red[32];
    const int row = blockIdx.x;
    const int tid = threadIdx.x;
    const float* x = &X[(size_t)row * DIM];

    float v[4];
    float s = 0.0f;
#pragma unroll
    for (int i = 0; i < 4; i++) { v[i] = x[tid + i * 128]; s += v[i]; }
#pragma unroll
    for (int off = 16; off > 0; off >>= 1)
        s += __shfl_xor_sync(0xffffffffu, s, off);
    if ((tid & 31) == 0) red[tid >> 5] = s;
    __syncthreads();
    if (tid < 32) {
        float t = (tid < 4) ? red[tid] : 0.0f;
#pragma unroll
        for (int off = 2; off > 0; off >>= 1)
            t += __shfl_xor_sync(0xffffffffu, t, off);
        if (tid == 0) red[0] = t;
    }
    __syncthreads();
    float mu = red[0] * (1.0f / DIM);

    float s2 = 0.0f;
#pragma unroll
    for (int i = 0; i < 4; i++) { float d = v[i] - mu; s2 += d * d; }
#pragma unroll
    for (int off = 16; off > 0; off >>= 1)
        s2 += __shfl_xor_sync(0xffffffffu, s2, off);
    __syncthreads();
    if ((tid & 31) == 0) red[tid >> 5] = s2;
    __syncthreads();
    if (tid < 32) {
        float t = (tid < 4) ? red[tid] : 0.0f;
#pragma unroll
        for (int off = 2; off > 0; off >>= 1)
            t += __shfl_xor_sync(0xffffffffu, t, off);
        if (tid == 0) red[0] = t;
    }
    __syncthreads();
    float rstd = rsqrtf(red[0] * (1.0f / DIM) + LN_EPS);
#pragma unroll
    for (int i = 0; i < 4; i++) {
        int c = tid + i * 128;
        out[(size_t)row * DIM + c] = (v[i] - mu) * rstd * gam[c] + bet[c];
    }
}

// ============================================================
extern "C" void kernel_launch(void* const* d_in, const int* in_sizes, int n_in,
                              void* d_out, int out_size)
{
    const float* query   = (const float*)d_in[0];
    const float* context = (const float*)d_in[1];
    const float* qcoord  = (const float*)d_in[2];
    const float* ccoord  = (const float*)d_in[3];
    const float* Wq = (const float*)d_in[4];
    const float* bq = (const float*)d_in[5];
    const float* Wk = (const float*)d_in[6];
    const float* bk = (const float*)d_in[7];
    const float* Wv = (const float*)d_in[8];
    const float* bv = (const float*)d_in[9];
    const float* Wo = (const float*)d_in[10];
    const float* bo = (const float*)d_in[11];
    const float* ln_g = (const float*)d_in[12];
    const float* ln_b = (const float*)d_in[13];
    const float* log_scale = (const float*)d_in[14];
    const float* bias_ph   = (const float*)d_in[15];
    float* out = (float*)d_out;

    __nv_bfloat16 *qin, *cin, *Wqb, *Wkb, *Wvb, *Wob, *Qb, *Kb, *Vb, *ctxb;
    float *po, *pm, *pl, *x;
    cudaGetSymbolAddress((void**)&qin,  g_qin);
    cudaGetSymbolAddress((void**)&cin,  g_cin);
    cudaGetSymbolAddress((void**)&Wqb,  g_Wqb);
    cudaGetSymbolAddress((void**)&Wkb,  g_Wkb);
    cudaGetSymbolAddress((void**)&Wvb,  g_Wvb);
    cudaGetSymbolAddress((void**)&Wob,  g_Wob);
    cudaGetSymbolAddress((void**)&Qb,   g_Qb);
    cudaGetSymbolAddress((void**)&Kb,   g_Kb);
    cudaGetSymbolAddress((void**)&Vb,   g_Vb);
    cudaGetSymbolAddress((void**)&ctxb, g_ctxb);
    cudaGetSymbolAddress((void**)&po,   g_po);
    cudaGetSymbolAddress((void**)&pm,   g_pm);
    cudaGetSymbolAddress((void**)&pl,   g_pl);
    cudaGetSymbolAddress((void**)&x,    g_x);

    // fp32 -> bf16 conversions
    conv_in2<<<(NQ * DIM / 4 + NC * DIM / 4) / 256, 256>>>(query, context, qin, cin);
    conv_w4<<<(4 * DIM * DIM / 4) / 256, 256>>>(Wq, Wk, Wv, Wo, Wqb, Wkb, Wvb, Wob);

    // fused QKV projections (tensor cores)
    qkv_mma_kernel<<<dim3(4, 32, 3), 256>>>(qin, cin, Wqb, bq, Wkb, bk, Wvb, bv,
                                            Qb, Kb, Vb);

    // flash attention, context split x2
    cudaFuncSetAttribute(attn_mma_kernel,
                         cudaFuncAttributeMaxDynamicSharedMemorySize, ATTN_SMEM);
    attn_mma_kernel<<<dim3(NQ / 128, NH, 2), 256, ATTN_SMEM>>>(
        Qb, Kb, Vb, qcoord, ccoord, log_scale, bias_ph, po, pm, pl);

    // merge splits -> bf16 ctx
    merge_kernel<<<NQ, 256>>>(po, pm, pl, ctxb);

    // output projection + residual (tensor cores, fp32 out)
    oproj_mma_kernel<<<dim3(4, 16), 256>>>(ctxb, Wob, bo, query, x);

    // LayerNorm
    ln_kernel<<<NQ, 128>>>(x, ln_g, ln_b, out);
}